// round 4
// baseline (speedup 1.0000x reference)
#include <cuda_runtime.h>
#include <cuda_bf16.h>
#include <math.h>

#define Bb   4
#define SS   1024
#define DD   1024
#define HH   16
#define HKK  8
#define HDD  64
#define FFF  3072
#define LL   4
#define NTOK (Bb*SS)
#define WIN_ 12

// ---------------- scratch (device globals: no allocations allowed) ----------
__device__ float g_h  [NTOK*DD];
__device__ float g_n  [NTOK*DD];
__device__ float g_q  [NTOK*HH*HDD];
__device__ float g_k  [NTOK*HKK*HDD];
__device__ float g_v  [NTOK*HKK*HDD];
__device__ float g_ctx[NTOK*HH*HDD];
__device__ float g_gate[(size_t)NTOK*FFF];
__device__ float g_up  [(size_t)NTOK*FFF];

// ---------------- packed f32x2 helpers --------------------------------------
__device__ __forceinline__ unsigned long long pk2(float lo, float hi){
    unsigned long long r; asm("mov.b64 %0,{%1,%2};" : "=l"(r) : "f"(lo), "f"(hi)); return r;
}
__device__ __forceinline__ void upk2(unsigned long long v, float& lo, float& hi){
    asm("mov.b64 {%0,%1},%2;" : "=f"(lo), "=f"(hi) : "l"(v));
}
__device__ __forceinline__ unsigned long long fma2(unsigned long long a, unsigned long long b, unsigned long long c){
    unsigned long long d; asm("fma.rn.f32x2 %0,%1,%2,%3;" : "=l"(d) : "l"(a), "l"(b), "l"(c)); return d;
}

// ---------------- RMSNorm over rows of width DD ------------------------------
__global__ void rmsnorm_k(const float* __restrict__ x, const float* __restrict__ w,
                          float* __restrict__ out){
    int row = blockIdx.x;
    const float4* xr = (const float4*)(x + (size_t)row * DD);
    float4 v = xr[threadIdx.x];                  // 256 threads * 4 = 1024
    float ss = v.x*v.x + v.y*v.y + v.z*v.z + v.w*v.w;
    __shared__ float red[8];
    #pragma unroll
    for(int o = 16; o; o >>= 1) ss += __shfl_xor_sync(~0u, ss, o);
    if((threadIdx.x & 31) == 0) red[threadIdx.x >> 5] = ss;
    __syncthreads();
    if(threadIdx.x < 8){
        float t = red[threadIdx.x];
        #pragma unroll
        for(int o = 4; o; o >>= 1) t += __shfl_xor_sync(0xff, t, o);
        if(threadIdx.x == 0) red[0] = rsqrtf(t / (float)DD + 1e-6f);
    }
    __syncthreads();
    float r = red[0];
    float4 wv = ((const float4*)w)[threadIdx.x];
    float4 o4 = make_float4(v.x*r*wv.x, v.y*r*wv.y, v.z*r*wv.z, v.w*r*wv.w);
    ((float4*)(out + (size_t)row * DD))[threadIdx.x] = o4;
}

// ---------------- GEMM: C[M,N] (+)= A[M,K] * B[K,N], 64x64x16 tiles ---------
template<int ACC>
__global__ void __launch_bounds__(256) gemm_k(const float* __restrict__ A,
                                              const float* __restrict__ Bw,
                                              float* __restrict__ C,
                                              int K, int N){
    __shared__ float As[16][68];
    __shared__ float Bs[16][68];
    const int tid = threadIdx.x;
    const int tx = tid & 15, ty = tid >> 4;
    const int bm = blockIdx.y << 6, bn = blockIdx.x << 6;
    unsigned long long acc[4][2];
    #pragma unroll
    for(int i = 0; i < 4; i++){ acc[i][0] = 0ull; acc[i][1] = 0ull; }
    const int ar = tid >> 2, ac = (tid & 3) << 2;
    const int br = tid >> 4, bc = (tid & 15) << 2;
    const float* Aptr = A + (size_t)(bm + ar) * K + ac;
    const float* Bptr = Bw + (size_t)br * N + bn + bc;

    for(int k0 = 0; k0 < K; k0 += 16){
        float4 av = *(const float4*)(Aptr + k0);
        float4 bv = *(const float4*)(Bptr + (size_t)k0 * N);
        As[ac+0][ar] = av.x; As[ac+1][ar] = av.y;
        As[ac+2][ar] = av.z; As[ac+3][ar] = av.w;
        *(float4*)&Bs[br][bc] = bv;
        __syncthreads();
        #pragma unroll
        for(int kk = 0; kk < 16; kk++){
            float4 a4 = *(const float4*)&As[kk][ty << 2];
            float4 b4 = *(const float4*)&Bs[kk][tx << 2];
            unsigned long long bp0 = pk2(b4.x, b4.y);
            unsigned long long bp1 = pk2(b4.z, b4.w);
            unsigned long long ap;
            ap = pk2(a4.x, a4.x); acc[0][0] = fma2(ap, bp0, acc[0][0]); acc[0][1] = fma2(ap, bp1, acc[0][1]);
            ap = pk2(a4.y, a4.y); acc[1][0] = fma2(ap, bp0, acc[1][0]); acc[1][1] = fma2(ap, bp1, acc[1][1]);
            ap = pk2(a4.z, a4.z); acc[2][0] = fma2(ap, bp0, acc[2][0]); acc[2][1] = fma2(ap, bp1, acc[2][1]);
            ap = pk2(a4.w, a4.w); acc[3][0] = fma2(ap, bp0, acc[3][0]); acc[3][1] = fma2(ap, bp1, acc[3][1]);
        }
        __syncthreads();
    }
    #pragma unroll
    for(int i = 0; i < 4; i++){
        float4 o;
        upk2(acc[i][0], o.x, o.y);
        upk2(acc[i][1], o.z, o.w);
        float* cp = C + (size_t)(bm + (ty << 2) + i) * N + bn + (tx << 2);
        if(ACC){
            float4 c = *(const float4*)cp;
            o.x += c.x; o.y += c.y; o.z += c.z; o.w += c.w;
        }
        *(float4*)cp = o;
    }
}

// ---------------- fused per-head QK RMSNorm + RoPE ---------------------------
__global__ void qknorm_rope_k(const float* __restrict__ qw, const float* __restrict__ kw){
    int wid  = (blockIdx.x * blockDim.x + threadIdx.x) >> 5;
    int lane = threadIdx.x & 31;
    const int total = NTOK * (HH + HKK);
    if(wid >= total) return;
    int token = wid / (HH + HKK);
    int head  = wid % (HH + HKK);
    float* base; const float* wn;
    if(head < HH){ base = g_q + ((size_t)token * HH + head) * HDD; wn = qw; }
    else         { base = g_k + ((size_t)token * HKK + (head - HH)) * HDD; wn = kw; }
    int s = token & (SS - 1);
    float x0 = base[lane], x1 = base[lane + 32];
    float ss = x0*x0 + x1*x1;
    #pragma unroll
    for(int o = 16; o; o >>= 1) ss += __shfl_xor_sync(~0u, ss, o);
    float r = rsqrtf(ss / (float)HDD + 1e-6f);
    x0 = x0 * r * wn[lane];
    x1 = x1 * r * wn[lane + 32];
    // inv_freq = theta^(-lane/32), theta = 1e6 ; ln(1e6)/32 = 0.43173470496...
    float inv = expf(-(float)lane * 0.431734704963f);
    float ang = (float)s * inv;
    float sn, cs; sincosf(ang, &sn, &cs);
    base[lane]      = x0 * cs - x1 * sn;
    base[lane + 32] = x1 * cs + x0 * sn;
}

// ---------------- attention: 16 queries per block, online softmax ------------
__device__ __forceinline__ float warp_max(float v){
    #pragma unroll
    for(int o = 16; o; o >>= 1) v = fmaxf(v, __shfl_xor_sync(~0u, v, o));
    return v;
}
__device__ __forceinline__ float warp_sum(float v){
    #pragma unroll
    for(int o = 16; o; o >>= 1) v += __shfl_xor_sync(~0u, v, o);
    return v;
}

__global__ void __launch_bounds__(256) attn_k(const int* __restrict__ amask, int win){
    __shared__ float Ks[64][65];
    __shared__ float Vs[64][65];
    __shared__ float qs[16][64];
    __shared__ float ps[16][64];
    __shared__ int   msk[64];
    const int b = blockIdx.z, h = blockIdx.y;
    const int q0 = blockIdx.x << 4;
    const int kvh = h >> 1;                 // H/HK = 2
    const int tid = threadIdx.x, lane = tid & 31, w = tid >> 5;

    for(int e = tid; e < 16 * 64; e += 256){
        int r = e >> 6, d = e & 63;
        qs[r][d] = g_q[(((size_t)(b * SS) + q0 + r) * HH + h) * HDD + d];
    }
    const int qA = q0 + 2 * w, qB = qA + 1;
    float mA = -1e30f, mB = -1e30f, sA = 0.f, sB = 0.f;
    float cA0 = 0.f, cA1 = 0.f, cB0 = 0.f, cB1 = 0.f;

    int kbeg = 0, kend = SS;
    if(win < SS){
        kbeg = max(0, q0 - win) & ~63;
        kend = min(SS, q0 + 15 + win + 1);
    }

    for(int kt = kbeg; kt < kend; kt += 64){
        for(int e = tid; e < 4096; e += 256){
            int r = e >> 6, d = e & 63;
            size_t gi = (((size_t)(b * SS) + kt + r) * HKK + kvh) * HDD + d;
            Ks[r][d] = g_k[gi];
            Vs[r][d] = g_v[gi];
        }
        if(tid < 64) msk[tid] = amask[b * SS + kt + tid];
        __syncthreads();

        float s0 = 0.f, s1 = 0.f, s2 = 0.f, s3 = 0.f;
        #pragma unroll 8
        for(int d = 0; d < 64; d++){
            float ka = Ks[lane][d],      kb = Ks[lane + 32][d];
            float qa = qs[2 * w][d],     qb = qs[2 * w + 1][d];
            s0 += qa * ka; s1 += qa * kb;
            s2 += qb * ka; s3 += qb * kb;
        }
        const float scale = 0.125f;
        const int j0 = kt + lane, j1 = j0 + 32;
        bool ok0 = msk[lane] > 0, ok1 = msk[lane + 32] > 0;
        bool full = (win >= SS);
        int dA0 = qA - j0; if(dA0 < 0) dA0 = -dA0;
        int dA1 = qA - j1; if(dA1 < 0) dA1 = -dA1;
        int dB0 = qB - j0; if(dB0 < 0) dB0 = -dB0;
        int dB1 = qB - j1; if(dB1 < 0) dB1 = -dB1;
        s0 = (ok0 && (full || dA0 <= win)) ? s0 * scale : -1e30f;
        s1 = (ok1 && (full || dA1 <= win)) ? s1 * scale : -1e30f;
        s2 = (ok0 && (full || dB0 <= win)) ? s2 * scale : -1e30f;
        s3 = (ok1 && (full || dB1 <= win)) ? s3 * scale : -1e30f;

        // online softmax: query A
        float tA = warp_max(fmaxf(s0, s1));
        float mnA = fmaxf(mA, tA);
        float pa0 = (s0 > -1e29f) ? expf(s0 - mnA) : 0.f;
        float pa1 = (s1 > -1e29f) ? expf(s1 - mnA) : 0.f;
        float corrA = expf(mA - mnA);
        sA = sA * corrA + warp_sum(pa0 + pa1);
        mA = mnA;
        // query B
        float tB = warp_max(fmaxf(s2, s3));
        float mnB = fmaxf(mB, tB);
        float pb0 = (s2 > -1e29f) ? expf(s2 - mnB) : 0.f;
        float pb1 = (s3 > -1e29f) ? expf(s3 - mnB) : 0.f;
        float corrB = expf(mB - mnB);
        sB = sB * corrB + warp_sum(pb0 + pb1);
        mB = mnB;

        ps[2 * w][lane]          = pa0;
        ps[2 * w][lane + 32]     = pa1;
        ps[2 * w + 1][lane]      = pb0;
        ps[2 * w + 1][lane + 32] = pb1;
        __syncwarp();

        cA0 *= corrA; cA1 *= corrA; cB0 *= corrB; cB1 *= corrB;
        #pragma unroll 8
        for(int k = 0; k < 64; k++){
            float pa = ps[2 * w][k], pb = ps[2 * w + 1][k];
            float v0 = Vs[k][lane], v1 = Vs[k][lane + 32];
            cA0 += pa * v0; cA1 += pa * v1;
            cB0 += pb * v0; cB1 += pb * v1;
        }
        __syncthreads();
    }

    float rA = (sA > 0.f) ? 1.f / sA : 0.f;
    float rB = (sB > 0.f) ? 1.f / sB : 0.f;
    size_t oA = (((size_t)(b * SS) + qA) * HH + h) * HDD;
    size_t oB = (((size_t)(b * SS) + qB) * HH + h) * HDD;
    g_ctx[oA + lane]      = cA0 * rA;
    g_ctx[oA + lane + 32] = cA1 * rA;
    g_ctx[oB + lane]      = cB0 * rB;
    g_ctx[oB + lane + 32] = cB1 * rB;
}

// ---------------- SiLU(gate) * up, in place into g_gate ----------------------
__global__ void silu_k(){
    size_t i = (size_t)blockIdx.x * blockDim.x + threadIdx.x;
    float4 g = ((const float4*)g_gate)[i];
    float4 u = ((const float4*)g_up)[i];
    g.x = g.x / (1.f + expf(-g.x)) * u.x;
    g.y = g.y / (1.f + expf(-g.y)) * u.y;
    g.z = g.z / (1.f + expf(-g.z)) * u.z;
    g.w = g.w / (1.f + expf(-g.w)) * u.w;
    ((float4*)g_gate)[i] = g;
}

// ---------------- driver -----------------------------------------------------
extern "C" void kernel_launch(void* const* d_in, const int* in_sizes, int n_in,
                              void* d_out, int out_size){
    const float* emb = (const float*)d_in[0];
    const float* wq  = (const float*)d_in[1];
    const float* wk  = (const float*)d_in[2];
    const float* wv  = (const float*)d_in[3];
    const float* wo  = (const float*)d_in[4];
    const float* qnw = (const float*)d_in[5];
    const float* knw = (const float*)d_in[6];
    const float* ln1 = (const float*)d_in[7];
    const float* ln2 = (const float*)d_in[8];
    const float* wg  = (const float*)d_in[9];
    const float* wu  = (const float*)d_in[10];
    const float* wd  = (const float*)d_in[11];
    const float* nw  = (const float*)d_in[12];
    const int*   am  = (const int*)d_in[13];

    float *p_h, *p_n, *p_q, *p_k, *p_v, *p_ctx, *p_gate, *p_up;
    cudaGetSymbolAddress((void**)&p_h,    g_h);
    cudaGetSymbolAddress((void**)&p_n,    g_n);
    cudaGetSymbolAddress((void**)&p_q,    g_q);
    cudaGetSymbolAddress((void**)&p_k,    g_k);
    cudaGetSymbolAddress((void**)&p_v,    g_v);
    cudaGetSymbolAddress((void**)&p_ctx,  g_ctx);
    cudaGetSymbolAddress((void**)&p_gate, g_gate);
    cudaGetSymbolAddress((void**)&p_up,   g_up);

    cudaMemcpyAsync(p_h, emb, sizeof(float) * (size_t)NTOK * DD,
                    cudaMemcpyDeviceToDevice);

    for(int l = 0; l < LL; l++){
        rmsnorm_k<<<NTOK, 256>>>(p_h, ln1 + (size_t)l * DD, p_n);
        gemm_k<0><<<dim3(16, 64), 256>>>(p_n, wq + (size_t)l * DD * (HH * HDD),  p_q, DD, HH * HDD);
        gemm_k<0><<<dim3( 8, 64), 256>>>(p_n, wk + (size_t)l * DD * (HKK * HDD), p_k, DD, HKK * HDD);
        gemm_k<0><<<dim3( 8, 64), 256>>>(p_n, wv + (size_t)l * DD * (HKK * HDD), p_v, DD, HKK * HDD);
        qknorm_rope_k<<<(NTOK * (HH + HKK)) / 4, 128>>>(qnw + (size_t)l * HDD, knw + (size_t)l * HDD);
        attn_k<<<dim3(SS / 16, HH, Bb), 256>>>(am, (l % 2 == 0) ? SS : WIN_);
        gemm_k<1><<<dim3(16, 64), 256>>>(p_ctx, wo + (size_t)l * (HH * HDD) * DD, p_h, HH * HDD, DD);
        rmsnorm_k<<<NTOK, 256>>>(p_h, ln2 + (size_t)l * DD, p_n);
        gemm_k<0><<<dim3(48, 64), 256>>>(p_n, wg + (size_t)l * DD * FFF, p_gate, DD, FFF);
        gemm_k<0><<<dim3(48, 64), 256>>>(p_n, wu + (size_t)l * DD * FFF, p_up,   DD, FFF);
        silu_k<<<((size_t)NTOK * FFF / 4) / 256, 256>>>();
        gemm_k<1><<<dim3(16, 64), 256>>>(p_gate, wd + (size_t)l * FFF * DD, p_h, FFF, DD);
    }
    rmsnorm_k<<<NTOK, 256>>>(p_h, nw, (float*)d_out);
}

// round 7
// speedup vs baseline: 2.1479x; 2.1479x over previous
#include <cuda_runtime.h>
#include <cuda_bf16.h>
#include <math.h>
#include <stdint.h>

#define Bb   4
#define SS   1024
#define DD   1024
#define HH   16
#define HKK  8
#define HDD  64
#define FFF  3072
#define LL   4
#define NTOK (Bb*SS)
#define WIN_ 12
#define QKVW 2048
#define GUW  6144

// ---------------- scratch (device globals; no allocations allowed) -----------
__device__ float g_h  [(size_t)NTOK*DD];
__device__ float g_n  [(size_t)NTOK*DD];
__device__ float g_qkv[(size_t)NTOK*QKVW];
__device__ float g_ctx[(size_t)NTOK*DD];
__device__ float g_gu [(size_t)NTOK*GUW];
__device__ float g_act[(size_t)NTOK*FFF];

// bf16 hi/lo split weights, transposed to [N][K]; per layer (elem offsets):
//  qkv: hi@0            plane=2048*1024          (2 planes)
//  wo : hi@4,194,304    plane=1,048,576
//  gu : hi@6,291,456    plane=6,291,456
//  dn : hi@18,874,368   plane=3,145,728
#define W2_QKV   0
#define W2_WO    4194304
#define W2_GU    6291456
#define W2_DN    18874368
#define W2_LAYER 25165824
__device__ __nv_bfloat16 g_wt[(size_t)LL*W2_LAYER];

// ---------------- helpers -----------------------------------------------------
__device__ __forceinline__ uint32_t smem_u32(const void* p){
    uint32_t a;
    asm("{ .reg .u64 t; cvta.to.shared.u64 t, %1; cvt.u32.u64 %0, t; }" : "=r"(a) : "l"(p));
    return a;
}
__device__ __forceinline__ uint32_t packbf(__nv_bfloat16 a, __nv_bfloat16 b){
    __nv_bfloat162 t(a, b);
    return *(uint32_t*)&t;
}

#define LDSM4(r, addr) \
    asm volatile("ldmatrix.sync.aligned.m8n8.x4.shared.b16 {%0,%1,%2,%3}, [%4];" \
        : "=r"((r)[0]), "=r"((r)[1]), "=r"((r)[2]), "=r"((r)[3]) : "r"(addr))

#define MMA16816(c, a, b0, b1) \
    asm volatile("mma.sync.aligned.m16n8k16.row.col.f32.bf16.bf16.f32 " \
        "{%0,%1,%2,%3}, {%4,%5,%6,%7}, {%8,%9}, {%0,%1,%2,%3};" \
        : "+f"((c)[0]), "+f"((c)[1]), "+f"((c)[2]), "+f"((c)[3]) \
        : "r"((a)[0]), "r"((a)[1]), "r"((a)[2]), "r"((a)[3]), "r"(b0), "r"(b1))

#define CPASYNC16(dst, src) \
    asm volatile("cp.async.cg.shared.global [%0], [%1], 16;" \
        :: "r"(dst), "l"((unsigned long long)__cvta_generic_to_global(src)))

// ============ GEMM: C[M,N] (+)= A[M,K] (fp32) * Bt[N,K]^T (bf16 hi/lo) =======
// CTA tile 128x128, BK=16, 256 threads (8 warps = 4m x 2n, 32x64 each).
// 3-split: acc += Ah*Bh + Ah*Bl + Al*Bh.
// smem per stage (bf16 elems): Ahi[0,2048) Alo[2048,4096) Bhi[4096,6144) Blo[6144,8192)
// row = 16 elems (32B), chunk(16B) swizzle: phys = c ^ ((row>>2)&1)
template<int ACC>
__global__ void __launch_bounds__(256) gemm_mma(const float* __restrict__ A,
        const __nv_bfloat16* __restrict__ Bt, float* __restrict__ C,
        int K, int N){
    __shared__ __align__(16) __nv_bfloat16 smbuf[2*8192];
    const int tid = threadIdx.x, lane = tid & 31, wid = tid >> 5;
    const int wm = (wid >> 1) << 5, wn = (wid & 1) << 6;
    const int bm = blockIdx.y << 7, bn = blockIdx.x << 7;
    const size_t NK = (size_t)N * K;
    const uint32_t sb = smem_u32(smbuf);

    float c[2][8][4];
    #pragma unroll
    for(int i = 0; i < 2; i++)
        #pragma unroll
        for(int j = 0; j < 8; j++){
            c[i][j][0] = 0.f; c[i][j][1] = 0.f; c[i][j][2] = 0.f; c[i][j][3] = 0.f;
        }

    float4 areg[2];
    const int arow = tid >> 2, aq = tid & 3;
    auto ldA = [&](int kt){
        const float* ap = A + (size_t)(bm + arow) * K + kt * 16 + (aq << 2);
        areg[0] = *(const float4*)ap;
        areg[1] = *(const float4*)(ap + (size_t)64 * K);
    };
    auto stA = [&](int s){
        #pragma unroll
        for(int i = 0; i < 2; i++){
            int row = arow + i * 64;
            uint32_t off = (uint32_t)(s * 8192 + row * 16 +
                           ((((aq >> 1) ^ ((row >> 2) & 1)) << 3) | ((aq & 1) << 2)));
            float v0 = areg[i].x, v1 = areg[i].y, v2 = areg[i].z, v3 = areg[i].w;
            __nv_bfloat16 h0 = __float2bfloat16(v0), h1 = __float2bfloat16(v1);
            __nv_bfloat16 h2 = __float2bfloat16(v2), h3 = __float2bfloat16(v3);
            __nv_bfloat16 l0 = __float2bfloat16(v0 - __bfloat162float(h0));
            __nv_bfloat16 l1 = __float2bfloat16(v1 - __bfloat162float(h1));
            __nv_bfloat16 l2 = __float2bfloat16(v2 - __bfloat162float(h2));
            __nv_bfloat16 l3 = __float2bfloat16(v3 - __bfloat162float(h3));
            uint2 uh = make_uint2(packbf(h0, h1), packbf(h2, h3));
            uint2 ul = make_uint2(packbf(l0, l1), packbf(l2, l3));
            *(uint2*)&smbuf[off]        = uh;
            *(uint2*)&smbuf[off + 2048] = ul;
        }
    };
    const int bseg0 = tid << 1;
    auto ldB = [&](int kt, int s){
        #pragma unroll
        for(int j = 0; j < 2; j++){
            int sidx = bseg0 + j;
            int plane = sidx >> 8;            // 0=hi,1=lo
            int row   = (sidx & 255) >> 1;
            int ch    = sidx & 1;
            const __nv_bfloat16* src = Bt + (size_t)plane * NK +
                                       (size_t)(bn + row) * K + kt * 16 + (ch << 3);
            uint32_t dst = sb + 2u * (uint32_t)(s * 8192 + 4096 + plane * 2048 +
                           row * 16 + ((ch ^ ((row >> 2) & 1)) << 3));
            CPASYNC16(dst, src);
        }
    };

    const int T = K >> 4;
    ldA(0); ldB(0, 0);
    asm volatile("cp.async.commit_group;");
    stA(0);

    for(int kt = 0; kt < T; kt++){
        const int s = kt & 1;
        if(kt + 1 < T){
            ldA(kt + 1);
            ldB(kt + 1, s ^ 1);
            asm volatile("cp.async.commit_group;");
            asm volatile("cp.async.wait_group 1;");
        } else {
            asm volatile("cp.async.wait_group 0;");
        }
        __syncthreads();

        // ---- compute on stage s ----
        {
            const uint32_t stg = sb + 2u * (uint32_t)(s * 8192);
            uint32_t a[2][2][4];                       // [plane][mt][4]
            #pragma unroll
            for(int p = 0; p < 2; p++)
                #pragma unroll
                for(int mt = 0; mt < 2; mt++){
                    int R = wm + mt * 16 + (lane & 15);
                    uint32_t addr = stg + 2u * (uint32_t)(p * 2048 + R * 16 +
                                    (((lane >> 4) ^ ((R >> 2) & 1)) << 3));
                    LDSM4(a[p][mt], addr);
                }
            #pragma unroll
            for(int ng = 0; ng < 4; ng++){
                int R = wn + ng * 16 + (lane & 7) + ((lane >> 4) << 3);
                int ch = (lane >> 3) & 1;
                uint32_t pc = (uint32_t)(((ch ^ ((R >> 2) & 1)) << 3) + R * 16);
                uint32_t bh[4], bl[4];
                LDSM4(bh, stg + 2u * (4096u + pc));
                LDSM4(bl, stg + 2u * (6144u + pc));
                #pragma unroll
                for(int mt = 0; mt < 2; mt++){
                    MMA16816(c[mt][2*ng],   a[0][mt], bh[0], bh[1]);   // hi*hi
                    MMA16816(c[mt][2*ng],   a[0][mt], bl[0], bl[1]);   // hi*lo
                    MMA16816(c[mt][2*ng],   a[1][mt], bh[0], bh[1]);   // lo*hi
                    MMA16816(c[mt][2*ng+1], a[0][mt], bh[2], bh[3]);
                    MMA16816(c[mt][2*ng+1], a[0][mt], bl[2], bl[3]);
                    MMA16816(c[mt][2*ng+1], a[1][mt], bh[2], bh[3]);
                }
            }
        }
        __syncthreads();
        if(kt + 1 < T) stA(s ^ 1);
    }

    // ---- epilogue ----
    #pragma unroll
    for(int mt = 0; mt < 2; mt++)
        #pragma unroll
        for(int nt = 0; nt < 8; nt++){
            int r  = bm + wm + mt * 16 + (lane >> 2);
            int cc = bn + wn + nt * 8 + ((lane & 3) << 1);
            float* p0 = C + (size_t)r * N + cc;
            float* p1 = C + (size_t)(r + 8) * N + cc;
            float2 v0 = make_float2(c[mt][nt][0], c[mt][nt][1]);
            float2 v1 = make_float2(c[mt][nt][2], c[mt][nt][3]);
            if(ACC){
                float2 o = *(const float2*)p0; v0.x += o.x; v0.y += o.y;
                o = *(const float2*)p1;        v1.x += o.x; v1.y += o.y;
            }
            *(float2*)p0 = v0;
            *(float2*)p1 = v1;
        }
}

// ---------------- transpose + bf16 hi/lo split: d[n][k] = split(src[k][n]) ----
__global__ void transpose_bf16(const float* __restrict__ src,
                               __nv_bfloat16* __restrict__ dhi,
                               __nv_bfloat16* __restrict__ dlo,
                               int K, int N){
    __shared__ float t[32][33];
    int k0 = blockIdx.y << 5, n0 = blockIdx.x << 5;
    int x = threadIdx.x, y = threadIdx.y;
    #pragma unroll
    for(int i = 0; i < 32; i += 8) t[y + i][x] = src[(size_t)(k0 + y + i) * N + n0 + x];
    __syncthreads();
    #pragma unroll
    for(int i = 0; i < 32; i += 8){
        float v = t[x][y + i];
        __nv_bfloat16 h = __float2bfloat16(v);
        __nv_bfloat16 l = __float2bfloat16(v - __bfloat162float(h));
        size_t o = (size_t)(n0 + y + i) * K + k0 + x;
        dhi[o] = h;
        dlo[o] = l;
    }
}

// ---------------- RMSNorm over rows of width DD ------------------------------
__global__ void rmsnorm_k(const float* __restrict__ x, const float* __restrict__ w,
                          float* __restrict__ out){
    int row = blockIdx.x;
    const float4* xr = (const float4*)(x + (size_t)row * DD);
    float4 v = xr[threadIdx.x];
    float ss = v.x*v.x + v.y*v.y + v.z*v.z + v.w*v.w;
    __shared__ float red[8];
    #pragma unroll
    for(int o = 16; o; o >>= 1) ss += __shfl_xor_sync(~0u, ss, o);
    if((threadIdx.x & 31) == 0) red[threadIdx.x >> 5] = ss;
    __syncthreads();
    if(threadIdx.x < 8){
        float t = red[threadIdx.x];
        #pragma unroll
        for(int o = 4; o; o >>= 1) t += __shfl_xor_sync(0xff, t, o);
        if(threadIdx.x == 0) red[0] = rsqrtf(t / (float)DD + 1e-6f);
    }
    __syncthreads();
    float r = red[0];
    float4 wv = ((const float4*)w)[threadIdx.x];
    float4 o4 = make_float4(v.x*r*wv.x, v.y*r*wv.y, v.z*r*wv.z, v.w*r*wv.w);
    ((float4*)(out + (size_t)row * DD))[threadIdx.x] = o4;
}

// ---------------- fused per-head QK RMSNorm + RoPE (packed qkv) --------------
__global__ void qknorm_rope_k(const float* __restrict__ qw, const float* __restrict__ kw){
    int wid  = (blockIdx.x * blockDim.x + threadIdx.x) >> 5;
    int lane = threadIdx.x & 31;
    const int total = NTOK * (HH + HKK);
    if(wid >= total) return;
    int token = wid / (HH + HKK);
    int head  = wid % (HH + HKK);
    float* base; const float* wn;
    if(head < HH){ base = g_qkv + (size_t)token * QKVW + head * HDD; wn = qw; }
    else         { base = g_qkv + (size_t)token * QKVW + 1024 + (head - HH) * HDD; wn = kw; }
    int s = token & (SS - 1);
    float x0 = base[lane], x1 = base[lane + 32];
    float ss = x0*x0 + x1*x1;
    #pragma unroll
    for(int o = 16; o; o >>= 1) ss += __shfl_xor_sync(~0u, ss, o);
    float r = rsqrtf(ss / (float)HDD + 1e-6f);
    x0 = x0 * r * wn[lane];
    x1 = x1 * r * wn[lane + 32];
    float inv = expf(-(float)lane * 0.431734704963f);   // ln(1e6)/32
    float ang = (float)s * inv;
    float sn, cs; sincosf(ang, &sn, &cs);
    base[lane]      = x0 * cs - x1 * sn;
    base[lane + 32] = x1 * cs + x0 * sn;
}

// ---------------- attention: 16 queries/block, online softmax ----------------
__device__ __forceinline__ float warp_max(float v){
    #pragma unroll
    for(int o = 16; o; o >>= 1) v = fmaxf(v, __shfl_xor_sync(~0u, v, o));
    return v;
}
__device__ __forceinline__ float warp_sum(float v){
    #pragma unroll
    for(int o = 16; o; o >>= 1) v += __shfl_xor_sync(~0u, v, o);
    return v;
}

__global__ void __launch_bounds__(256) attn_k(const int* __restrict__ amask, int win){
    __shared__ float Ks[64][65];
    __shared__ float Vs[64][65];
    __shared__ float qs[16][64];
    __shared__ float ps[16][64];
    __shared__ int   msk[64];
    const int b = blockIdx.z, h = blockIdx.y;
    const int q0 = blockIdx.x << 4;
    const int kvh = h >> 1;
    const int tid = threadIdx.x, lane = tid & 31, w = tid >> 5;

    for(int e = tid; e < 16 * 64; e += 256){
        int r = e >> 6, d = e & 63;
        qs[r][d] = g_qkv[((size_t)(b * SS) + q0 + r) * QKVW + h * HDD + d];
    }
    const int qA = q0 + 2 * w, qB = qA + 1;
    float mA = -1e30f, mB = -1e30f, sA = 0.f, sB = 0.f;
    float cA0 = 0.f, cA1 = 0.f, cB0 = 0.f, cB1 = 0.f;

    int kbeg = 0, kend = SS;
    if(win < SS){
        kbeg = max(0, q0 - win) & ~63;
        kend = min(SS, q0 + 15 + win + 1);
    }

    for(int kt = kbeg; kt < kend; kt += 64){
        for(int e = tid; e < 4096; e += 256){
            int r = e >> 6, d = e & 63;
            size_t gi = ((size_t)(b * SS) + kt + r) * QKVW + 1024 + kvh * HDD + d;
            Ks[r][d] = g_qkv[gi];
            Vs[r][d] = g_qkv[gi + 512];
        }
        if(tid < 64) msk[tid] = amask[b * SS + kt + tid];
        __syncthreads();

        float s0 = 0.f, s1 = 0.f, s2 = 0.f, s3 = 0.f;
        #pragma unroll 8
        for(int d = 0; d < 64; d++){
            float ka = Ks[lane][d],      kb = Ks[lane + 32][d];
            float qa = qs[2 * w][d],     qb = qs[2 * w + 1][d];
            s0 += qa * ka; s1 += qa * kb;
            s2 += qb * ka; s3 += qb * kb;
        }
        const float scale = 0.125f;
        const int j0 = kt + lane, j1 = j0 + 32;
        bool ok0 = msk[lane] > 0, ok1 = msk[lane + 32] > 0;
        bool full = (win >= SS);
        int dA0 = abs(qA - j0), dA1 = abs(qA - j1);
        int dB0 = abs(qB - j0), dB1 = abs(qB - j1);
        s0 = (ok0 && (full || dA0 <= win)) ? s0 * scale : -1e30f;
        s1 = (ok1 && (full || dA1 <= win)) ? s1 * scale : -1e30f;
        s2 = (ok0 && (full || dB0 <= win)) ? s2 * scale : -1e30f;
        s3 = (ok1 && (full || dB1 <= win)) ? s3 * scale : -1e30f;

        float tA = warp_max(fmaxf(s0, s1));
        float mnA = fmaxf(mA, tA);
        float pa0 = (s0 > -1e29f) ? expf(s0 - mnA) : 0.f;
        float pa1 = (s1 > -1e29f) ? expf(s1 - mnA) : 0.f;
        float corrA = expf(mA - mnA);
        sA = sA * corrA + warp_sum(pa0 + pa1);
        mA = mnA;
        float tB = warp_max(fmaxf(s2, s3));
        float mnB = fmaxf(mB, tB);
        float pb0 = (s2 > -1e29f) ? expf(s2 - mnB) : 0.f;
        float pb1 = (s3 > -1e29f) ? expf(s3 - mnB) : 0.f;
        float corrB = expf(mB - mnB);
        sB = sB * corrB + warp_sum(pb0 + pb1);
        mB = mnB;

        ps[2 * w][lane]          = pa0;
        ps[2 * w][lane + 32]     = pa1;
        ps[2 * w + 1][lane]      = pb0;
        ps[2 * w + 1][lane + 32] = pb1;
        __syncwarp();

        cA0 *= corrA; cA1 *= corrA; cB0 *= corrB; cB1 *= corrB;
        #pragma unroll 8
        for(int k = 0; k < 64; k++){
            float pa = ps[2 * w][k], pb = ps[2 * w + 1][k];
            float v0 = Vs[k][lane], v1 = Vs[k][lane + 32];
            cA0 += pa * v0; cA1 += pa * v1;
            cB0 += pb * v0; cB1 += pb * v1;
        }
        __syncthreads();
    }

    float rA = (sA > 0.f) ? 1.f / sA : 0.f;
    float rB = (sB > 0.f) ? 1.f / sB : 0.f;
    size_t oA = (((size_t)(b * SS) + qA) * HH + h) * HDD;
    size_t oB = (((size_t)(b * SS) + qB) * HH + h) * HDD;
    g_ctx[oA + lane]      = cA0 * rA;
    g_ctx[oA + lane + 32] = cA1 * rA;
    g_ctx[oB + lane]      = cB0 * rB;
    g_ctx[oB + lane + 32] = cB1 * rB;
}

// ---------------- SiLU(gate) * up -> g_act -----------------------------------
__global__ void silu_k(){
    size_t i = (size_t)blockIdx.x * blockDim.x + threadIdx.x;  // float4 index
    size_t row = i / (FFF/4);
    int    c   = (int)(i % (FFF/4));
    const float4* gp = (const float4*)(g_gu + row * GUW);
    float4 g = gp[c];
    float4 u = gp[c + FFF/4];
    g.x = g.x / (1.f + expf(-g.x)) * u.x;
    g.y = g.y / (1.f + expf(-g.y)) * u.y;
    g.z = g.z / (1.f + expf(-g.z)) * u.z;
    g.w = g.w / (1.f + expf(-g.w)) * u.w;
    ((float4*)g_act)[i] = g;
}

// ---------------- driver -----------------------------------------------------
extern "C" void kernel_launch(void* const* d_in, const int* in_sizes, int n_in,
                              void* d_out, int out_size){
    const float* emb = (const float*)d_in[0];
    const float* wq  = (const float*)d_in[1];
    const float* wk  = (const float*)d_in[2];
    const float* wv  = (const float*)d_in[3];
    const float* wo  = (const float*)d_in[4];
    const float* qnw = (const float*)d_in[5];
    const float* knw = (const float*)d_in[6];
    const float* ln1 = (const float*)d_in[7];
    const float* ln2 = (const float*)d_in[8];
    const float* wg  = (const float*)d_in[9];
    const float* wu  = (const float*)d_in[10];
    const float* wd  = (const float*)d_in[11];
    const float* nw  = (const float*)d_in[12];
    const int*   am  = (const int*)d_in[13];

    float *p_h, *p_n, *p_qkv, *p_ctx, *p_gu, *p_act;
    __nv_bfloat16* p_wt;
    cudaGetSymbolAddress((void**)&p_h,   g_h);
    cudaGetSymbolAddress((void**)&p_n,   g_n);
    cudaGetSymbolAddress((void**)&p_qkv, g_qkv);
    cudaGetSymbolAddress((void**)&p_ctx, g_ctx);
    cudaGetSymbolAddress((void**)&p_gu,  g_gu);
    cudaGetSymbolAddress((void**)&p_act, g_act);
    cudaGetSymbolAddress((void**)&p_wt,  g_wt);

    cudaMemcpyAsync(p_h, emb, sizeof(float) * (size_t)NTOK * DD,
                    cudaMemcpyDeviceToDevice);

    dim3 tb(32, 8);
    // pre-transpose + bf16-split all weights into [N][K] hi/lo planes
    for(int l = 0; l < LL; l++){
        __nv_bfloat16* wb = p_wt + (size_t)l * W2_LAYER;
        // qkv packed: N_total=2048, plane stride 2048*1024
        transpose_bf16<<<dim3(32, 32), tb>>>(wq + (size_t)l*1024*1024,
            wb + W2_QKV,                 wb + W2_QKV + 2097152,                 1024, 1024);
        transpose_bf16<<<dim3(16, 32), tb>>>(wk + (size_t)l*1024*512,
            wb + W2_QKV + 1048576,       wb + W2_QKV + 2097152 + 1048576,      1024, 512);
        transpose_bf16<<<dim3(16, 32), tb>>>(wv + (size_t)l*1024*512,
            wb + W2_QKV + 1572864,       wb + W2_QKV + 2097152 + 1572864,      1024, 512);
        transpose_bf16<<<dim3(32, 32), tb>>>(wo + (size_t)l*1024*1024,
            wb + W2_WO,                  wb + W2_WO + 1048576,                 1024, 1024);
        // gate|up packed: N_total=6144, plane stride 6144*1024
        transpose_bf16<<<dim3(96, 32), tb>>>(wg + (size_t)l*1024*FFF,
            wb + W2_GU,                  wb + W2_GU + 6291456,                 1024, 3072);
        transpose_bf16<<<dim3(96, 32), tb>>>(wu + (size_t)l*1024*FFF,
            wb + W2_GU + 3145728,        wb + W2_GU + 6291456 + 3145728,       1024, 3072);
        transpose_bf16<<<dim3(32, 96), tb>>>(wd + (size_t)l*FFF*1024,
            wb + W2_DN,                  wb + W2_DN + 3145728,                 3072, 1024);
    }

    for(int l = 0; l < LL; l++){
        __nv_bfloat16* wb = p_wt + (size_t)l * W2_LAYER;
        rmsnorm_k<<<NTOK, 256>>>(p_h, ln1 + (size_t)l * DD, p_n);
        gemm_mma<0><<<dim3(16, 32), 256>>>(p_n, wb + W2_QKV, p_qkv, 1024, QKVW);
        qknorm_rope_k<<<(NTOK * (HH + HKK)) / 4, 128>>>(qnw + (size_t)l * HDD,
                                                        knw + (size_t)l * HDD);
        attn_k<<<dim3(SS / 16, HH, Bb), 256>>>(am, (l % 2 == 0) ? SS : WIN_);
        gemm_mma<1><<<dim3(8, 32), 256>>>(p_ctx, wb + W2_WO, p_h, 1024, 1024);
        rmsnorm_k<<<NTOK, 256>>>(p_h, ln2 + (size_t)l * DD, p_n);
        gemm_mma<0><<<dim3(48, 32), 256>>>(p_n, wb + W2_GU, p_gu, 1024, GUW);
        silu_k<<<(int)(((size_t)NTOK * FFF / 4) / 256), 256>>>();
        gemm_mma<1><<<dim3(8, 32), 256>>>(p_act, wb + W2_DN, p_h, 3072, 1024);
    }
    rmsnorm_k<<<NTOK, 256>>>(p_h, nw, (float*)d_out);
}

// round 8
// speedup vs baseline: 2.3536x; 1.0958x over previous
#include <cuda_runtime.h>
#include <cuda_bf16.h>
#include <math.h>
#include <stdint.h>

#define Bb   4
#define SS   1024
#define DD   1024
#define HH   16
#define HKK  8
#define HDD  64
#define FFF  3072
#define LL   4
#define NTOK (Bb*SS)
#define WIN_ 12
#define QKVW 2048
#define GUW  6144

// ---------------- scratch (device globals; no allocations allowed) -----------
__device__ float g_h  [(size_t)NTOK*DD];
__device__ float g_qkv[(size_t)NTOK*QKVW];
__device__ float g_gu [(size_t)NTOK*GUW];
// bf16 hi/lo activation planes (hi at 0, lo at plane stride)
__device__ __nv_bfloat16 g_nbf[(size_t)2*NTOK*DD];
__device__ __nv_bfloat16 g_cbf[(size_t)2*NTOK*DD];
__device__ __nv_bfloat16 g_abf[(size_t)2*NTOK*FFF];

// bf16 hi/lo split weights, transposed to [N][K]; per layer (elem offsets):
#define W2_QKV   0
#define W2_WO    4194304
#define W2_GU    6291456
#define W2_DN    18874368
#define W2_LAYER 25165824
__device__ __nv_bfloat16 g_wt[(size_t)LL*W2_LAYER];

// ---------------- helpers -----------------------------------------------------
__device__ __forceinline__ uint32_t smem_u32(const void* p){
    uint32_t a;
    asm("{ .reg .u64 t; cvta.to.shared.u64 t, %1; cvt.u32.u64 %0, t; }" : "=r"(a) : "l"(p));
    return a;
}
__device__ __forceinline__ uint32_t packbf(__nv_bfloat16 a, __nv_bfloat16 b){
    __nv_bfloat162 t(a, b);
    return *(uint32_t*)&t;
}
__device__ __forceinline__ void split4(float4 v, uint2& uh, uint2& ul){
    __nv_bfloat16 h0 = __float2bfloat16(v.x), h1 = __float2bfloat16(v.y);
    __nv_bfloat16 h2 = __float2bfloat16(v.z), h3 = __float2bfloat16(v.w);
    __nv_bfloat16 l0 = __float2bfloat16(v.x - __bfloat162float(h0));
    __nv_bfloat16 l1 = __float2bfloat16(v.y - __bfloat162float(h1));
    __nv_bfloat16 l2 = __float2bfloat16(v.z - __bfloat162float(h2));
    __nv_bfloat16 l3 = __float2bfloat16(v.w - __bfloat162float(h3));
    uh = make_uint2(packbf(h0, h1), packbf(h2, h3));
    ul = make_uint2(packbf(l0, l1), packbf(l2, l3));
}

#define LDSM4(r, addr) \
    asm volatile("ldmatrix.sync.aligned.m8n8.x4.shared.b16 {%0,%1,%2,%3}, [%4];" \
        : "=r"((r)[0]), "=r"((r)[1]), "=r"((r)[2]), "=r"((r)[3]) : "r"(addr))

#define MMA16816(c, a, b0, b1) \
    asm volatile("mma.sync.aligned.m16n8k16.row.col.f32.bf16.bf16.f32 " \
        "{%0,%1,%2,%3}, {%4,%5,%6,%7}, {%8,%9}, {%0,%1,%2,%3};" \
        : "+f"((c)[0]), "+f"((c)[1]), "+f"((c)[2]), "+f"((c)[3]) \
        : "r"((a)[0]), "r"((a)[1]), "r"((a)[2]), "r"((a)[3]), "r"(b0), "r"(b1))

#define CPASYNC16(dst, src) \
    asm volatile("cp.async.cg.shared.global [%0], [%1], 16;" \
        :: "r"(dst), "l"((unsigned long long)__cvta_generic_to_global(src)))

// ============ GEMM: C[M,N] (+)= A[M,K] * Bt[N,K]^T, both bf16 hi/lo ==========
// CTA tile 128x128, BK=32 per stage, 2 stages, 256 threads (8 warps = 4m x 2n).
// 3-split: acc += Ah*Bh + Ah*Bl + Al*Bh.
// stage layout (bf16 elems, 16384/stage): Ahi@0 Alo@4096 Bhi@8192 Blo@12288.
// row = 32 elems (4 chunks of 16B); phys chunk = clog ^ ((row>>1)&3).
template<int ACC>
__global__ void __launch_bounds__(256, 2) gemm_mma(
        const __nv_bfloat16* __restrict__ A, size_t AMK,
        const __nv_bfloat16* __restrict__ Bt, float* __restrict__ C,
        int K, int N){
    extern __shared__ __align__(16) __nv_bfloat16 smg[];
    const int tid = threadIdx.x, lane = tid & 31, wid = tid >> 5;
    const int wm = (wid >> 1) << 5, wn = (wid & 1) << 6;
    const int bm = blockIdx.y << 7, bn = blockIdx.x << 7;
    const size_t NK = (size_t)N * K;
    const uint32_t sb = smem_u32(smg);

    float c[2][8][4];
    #pragma unroll
    for(int i = 0; i < 2; i++)
        #pragma unroll
        for(int j = 0; j < 8; j++){
            c[i][j][0] = 0.f; c[i][j][1] = 0.f; c[i][j][2] = 0.f; c[i][j][3] = 0.f;
        }

    const int cid0 = tid << 1;
    auto prefetch = [&](int s, int kt){
        #pragma unroll
        for(int rg = 0; rg < 4; rg++){
            #pragma unroll
            for(int j = 0; j < 2; j++){
                int cid = cid0 | j;               // 0..511 per region
                int row = cid >> 2, ch = cid & 3;
                const __nv_bfloat16* src;
                if(rg < 2) src = A  + (rg == 1 ? AMK : 0) + (size_t)(bm + row) * K + kt * 32 + (ch << 3);
                else       src = Bt + (rg == 3 ? NK  : 0) + (size_t)(bn + row) * K + kt * 32 + (ch << 3);
                uint32_t dst = sb + 2u * (uint32_t)(s * 16384 + rg * 4096 +
                               row * 32 + ((ch ^ ((row >> 1) & 3)) << 3));
                CPASYNC16(dst, src);
            }
        }
    };

    const int T = K >> 5;
    prefetch(0, 0);
    asm volatile("cp.async.commit_group;");

    for(int kt = 0; kt < T; kt++){
        const int s = kt & 1;
        if(kt + 1 < T){
            prefetch(s ^ 1, kt + 1);
            asm volatile("cp.async.commit_group;");
            asm volatile("cp.async.wait_group 1;");
        } else {
            asm volatile("cp.async.wait_group 0;");
        }
        __syncthreads();

        const uint32_t stg = sb + 2u * (uint32_t)(s * 16384);
        #pragma unroll
        for(int kk = 0; kk < 2; kk++){
            uint32_t a[2][2][4];                      // [plane][mt][4]
            #pragma unroll
            for(int p = 0; p < 2; p++)
                #pragma unroll
                for(int mt = 0; mt < 2; mt++){
                    int R = wm + mt * 16 + (lane & 15);
                    int phys = (kk * 2 + (lane >> 4)) ^ ((R >> 1) & 3);
                    LDSM4(a[p][mt], stg + 2u * (uint32_t)(p * 4096 + R * 32 + (phys << 3)));
                }
            #pragma unroll
            for(int ng = 0; ng < 4; ng++){
                int R = wn + ng * 16 + (lane & 7) + ((lane >> 4) << 3);
                int phys = (kk * 2 + ((lane >> 3) & 1)) ^ ((R >> 1) & 3);
                uint32_t pc = (uint32_t)(R * 32 + (phys << 3));
                uint32_t bh[4], bl[4];
                LDSM4(bh, stg + 2u * (8192u + pc));
                LDSM4(bl, stg + 2u * (12288u + pc));
                #pragma unroll
                for(int mt = 0; mt < 2; mt++){
                    MMA16816(c[mt][2*ng],   a[0][mt], bh[0], bh[1]);   // hi*hi
                    MMA16816(c[mt][2*ng],   a[0][mt], bl[0], bl[1]);   // hi*lo
                    MMA16816(c[mt][2*ng],   a[1][mt], bh[0], bh[1]);   // lo*hi
                    MMA16816(c[mt][2*ng+1], a[0][mt], bh[2], bh[3]);
                    MMA16816(c[mt][2*ng+1], a[0][mt], bl[2], bl[3]);
                    MMA16816(c[mt][2*ng+1], a[1][mt], bh[2], bh[3]);
                }
            }
        }
        __syncthreads();
    }

    // ---- epilogue ----
    #pragma unroll
    for(int mt = 0; mt < 2; mt++)
        #pragma unroll
        for(int nt = 0; nt < 8; nt++){
            int r  = bm + wm + mt * 16 + (lane >> 2);
            int cc = bn + wn + nt * 8 + ((lane & 3) << 1);
            float* p0 = C + (size_t)r * N + cc;
            float* p1 = C + (size_t)(r + 8) * N + cc;
            float2 v0 = make_float2(c[mt][nt][0], c[mt][nt][1]);
            float2 v1 = make_float2(c[mt][nt][2], c[mt][nt][3]);
            if(ACC){
                float2 o = *(const float2*)p0; v0.x += o.x; v0.y += o.y;
                o = *(const float2*)p1;        v1.x += o.x; v1.y += o.y;
            }
            *(float2*)p0 = v0;
            *(float2*)p1 = v1;
        }
}

// ---------------- transpose + bf16 hi/lo split: d[n][k] = split(src[k][n]) ----
__global__ void transpose_bf16(const float* __restrict__ src,
                               __nv_bfloat16* __restrict__ dhi,
                               __nv_bfloat16* __restrict__ dlo,
                               int K, int N){
    __shared__ float t[32][33];
    int k0 = blockIdx.y << 5, n0 = blockIdx.x << 5;
    int x = threadIdx.x, y = threadIdx.y;
    #pragma unroll
    for(int i = 0; i < 32; i += 8) t[y + i][x] = src[(size_t)(k0 + y + i) * N + n0 + x];
    __syncthreads();
    #pragma unroll
    for(int i = 0; i < 32; i += 8){
        float v = t[x][y + i];
        __nv_bfloat16 h = __float2bfloat16(v);
        __nv_bfloat16 l = __float2bfloat16(v - __bfloat162float(h));
        size_t o = (size_t)(n0 + y + i) * K + k0 + x;
        dhi[o] = h;
        dlo[o] = l;
    }
}

// ---------------- RMSNorm over rows of width DD ------------------------------
// BF=1: write bf16 hi/lo planes; BF=0: write fp32
template<int BF>
__global__ void rmsnorm_k(const float* __restrict__ x, const float* __restrict__ w,
                          float* __restrict__ out,
                          __nv_bfloat16* __restrict__ oh, __nv_bfloat16* __restrict__ ol){
    int row = blockIdx.x;
    const float4* xr = (const float4*)(x + (size_t)row * DD);
    float4 v = xr[threadIdx.x];
    float ss = v.x*v.x + v.y*v.y + v.z*v.z + v.w*v.w;
    __shared__ float red[8];
    #pragma unroll
    for(int o = 16; o; o >>= 1) ss += __shfl_xor_sync(~0u, ss, o);
    if((threadIdx.x & 31) == 0) red[threadIdx.x >> 5] = ss;
    __syncthreads();
    if(threadIdx.x < 8){
        float t = red[threadIdx.x];
        #pragma unroll
        for(int o = 4; o; o >>= 1) t += __shfl_xor_sync(0xff, t, o);
        if(threadIdx.x == 0) red[0] = rsqrtf(t / (float)DD + 1e-6f);
    }
    __syncthreads();
    float r = red[0];
    float4 wv = ((const float4*)w)[threadIdx.x];
    float4 o4 = make_float4(v.x*r*wv.x, v.y*r*wv.y, v.z*r*wv.z, v.w*r*wv.w);
    if(BF){
        uint2 uh, ul;
        split4(o4, uh, ul);
        size_t e = (size_t)row * DD + (threadIdx.x << 2);
        *(uint2*)&oh[e] = uh;
        *(uint2*)&ol[e] = ul;
    } else {
        ((float4*)(out + (size_t)row * DD))[threadIdx.x] = o4;
    }
}

// ---------------- fused per-head QK RMSNorm + RoPE (packed qkv) --------------
__global__ void qknorm_rope_k(const float* __restrict__ qw, const float* __restrict__ kw){
    int wid  = (blockIdx.x * blockDim.x + threadIdx.x) >> 5;
    int lane = threadIdx.x & 31;
    const int total = NTOK * (HH + HKK);
    if(wid >= total) return;
    int token = wid / (HH + HKK);
    int head  = wid % (HH + HKK);
    float* base; const float* wn;
    if(head < HH){ base = g_qkv + (size_t)token * QKVW + head * HDD; wn = qw; }
    else         { base = g_qkv + (size_t)token * QKVW + 1024 + (head - HH) * HDD; wn = kw; }
    int s = token & (SS - 1);
    float x0 = base[lane], x1 = base[lane + 32];
    float ss = x0*x0 + x1*x1;
    #pragma unroll
    for(int o = 16; o; o >>= 1) ss += __shfl_xor_sync(~0u, ss, o);
    float r = rsqrtf(ss / (float)HDD + 1e-6f);
    x0 = x0 * r * wn[lane];
    x1 = x1 * r * wn[lane + 32];
    float inv = expf(-(float)lane * 0.431734704963f);   // ln(1e6)/32
    float ang = (float)s * inv;
    float sn, cs; sincosf(ang, &sn, &cs);
    base[lane]      = x0 * cs - x1 * sn;
    base[lane + 32] = x1 * cs + x0 * sn;
}

// ---------------- attention: 32 queries/block, online softmax ----------------
__device__ __forceinline__ float warp_max(float v){
    #pragma unroll
    for(int o = 16; o; o >>= 1) v = fmaxf(v, __shfl_xor_sync(~0u, v, o));
    return v;
}
__device__ __forceinline__ float warp_sum(float v){
    #pragma unroll
    for(int o = 16; o; o >>= 1) v += __shfl_xor_sync(~0u, v, o);
    return v;
}

// dyn smem: Ks[64][65] Vs[64][65] qs[32][64] ps[32][64] msk[64]
#define ATT_SMEM ((4160*2 + 2048*2 + 64) * 4)
__global__ void __launch_bounds__(256) attn_k(const int* __restrict__ amask, int win,
        __nv_bfloat16* __restrict__ ch, __nv_bfloat16* __restrict__ cl){
    extern __shared__ float sm[];
    float (*Ks)[65] = (float(*)[65])sm;
    float (*Vs)[65] = (float(*)[65])(sm + 4160);
    float (*qs)[64] = (float(*)[64])(sm + 8320);
    float (*ps)[64] = (float(*)[64])(sm + 10368);
    int*   msk      = (int*)(sm + 12416);
    const int b = blockIdx.z, h = blockIdx.y;
    const int q0 = blockIdx.x << 5;
    const int kvh = h >> 1;
    const int tid = threadIdx.x, lane = tid & 31, w = tid >> 5;

    for(int e = tid; e < 32 * 64; e += 256){
        int r = e >> 6, d = e & 63;
        qs[r][d] = g_qkv[((size_t)(b * SS) + q0 + r) * QKVW + h * HDD + d];
    }
    const int qbase = q0 + 4 * w;
    float m[4], sum[4], c0[4], c1[4];
    #pragma unroll
    for(int i = 0; i < 4; i++){ m[i] = -1e30f; sum[i] = 0.f; c0[i] = 0.f; c1[i] = 0.f; }

    int kbeg = 0, kend = SS;
    if(win < SS){
        kbeg = max(0, q0 - win) & ~63;
        kend = min(SS, q0 + 31 + win + 1);
    }
    const bool full = (win >= SS);

    for(int kt = kbeg; kt < kend; kt += 64){
        for(int e = tid; e < 4096; e += 256){
            int r = e >> 6, d = e & 63;
            size_t gi = ((size_t)(b * SS) + kt + r) * QKVW + 1024 + kvh * HDD + d;
            Ks[r][d] = g_qkv[gi];
            Vs[r][d] = g_qkv[gi + 512];
        }
        if(tid < 64) msk[tid] = amask[b * SS + kt + tid];
        __syncthreads();

        float s[4][2];
        #pragma unroll
        for(int i = 0; i < 4; i++){ s[i][0] = 0.f; s[i][1] = 0.f; }
        #pragma unroll 8
        for(int d = 0; d < 64; d++){
            float ka = Ks[lane][d], kb = Ks[lane + 32][d];
            #pragma unroll
            for(int i = 0; i < 4; i++){
                float q = qs[4 * w + i][d];
                s[i][0] += q * ka;
                s[i][1] += q * kb;
            }
        }
        const float scale = 0.125f;
        const int j0 = kt + lane, j1 = j0 + 32;
        bool ok0 = msk[lane] > 0, ok1 = msk[lane + 32] > 0;
        #pragma unroll
        for(int i = 0; i < 4; i++){
            int qi = qbase + i;
            int d0 = abs(qi - j0), d1 = abs(qi - j1);
            float v0 = (ok0 && (full || d0 <= win)) ? s[i][0] * scale : -1e30f;
            float v1 = (ok1 && (full || d1 <= win)) ? s[i][1] * scale : -1e30f;
            float t = warp_max(fmaxf(v0, v1));
            float mn = fmaxf(m[i], t);
            float p0 = (v0 > -1e29f) ? expf(v0 - mn) : 0.f;
            float p1 = (v1 > -1e29f) ? expf(v1 - mn) : 0.f;
            float corr = expf(m[i] - mn);
            sum[i] = sum[i] * corr + warp_sum(p0 + p1);
            m[i] = mn;
            c0[i] *= corr; c1[i] *= corr;
            ps[4 * w + i][lane]      = p0;
            ps[4 * w + i][lane + 32] = p1;
        }
        __syncwarp();
        #pragma unroll 8
        for(int k = 0; k < 64; k++){
            float v0 = Vs[k][lane], v1 = Vs[k][lane + 32];
            #pragma unroll
            for(int i = 0; i < 4; i++){
                float p = ps[4 * w + i][k];
                c0[i] += p * v0;
                c1[i] += p * v1;
            }
        }
        __syncthreads();
    }

    #pragma unroll
    for(int i = 0; i < 4; i++){
        float r = (sum[i] > 0.f) ? 1.f / sum[i] : 0.f;
        float a = c0[i] * r, bv = c1[i] * r;
        size_t o = ((size_t)(b * SS) + qbase + i) * DD + h * HDD;
        __nv_bfloat16 ha = __float2bfloat16(a);
        __nv_bfloat16 hb = __float2bfloat16(bv);
        ch[o + lane]      = ha;
        ch[o + lane + 32] = hb;
        cl[o + lane]      = __float2bfloat16(a  - __bfloat162float(ha));
        cl[o + lane + 32] = __float2bfloat16(bv - __bfloat162float(hb));
    }
}

// ---------------- SiLU(gate) * up -> bf16 hi/lo planes -----------------------
__global__ void silu_k(__nv_bfloat16* __restrict__ oh, __nv_bfloat16* __restrict__ ol){
    size_t i = (size_t)blockIdx.x * blockDim.x + threadIdx.x;   // float4 idx
    size_t row = i / (FFF/4);
    int    c   = (int)(i % (FFF/4));
    const float4* gp = (const float4*)(g_gu + row * GUW);
    float4 g = gp[c];
    float4 u = gp[c + FFF/4];
    g.x = g.x / (1.f + expf(-g.x)) * u.x;
    g.y = g.y / (1.f + expf(-g.y)) * u.y;
    g.z = g.z / (1.f + expf(-g.z)) * u.z;
    g.w = g.w / (1.f + expf(-g.w)) * u.w;
    uint2 uh, ul;
    split4(g, uh, ul);
    size_t e = row * FFF + ((size_t)c << 2);
    *(uint2*)&oh[e] = uh;
    *(uint2*)&ol[e] = ul;
}

// ---------------- driver -----------------------------------------------------
extern "C" void kernel_launch(void* const* d_in, const int* in_sizes, int n_in,
                              void* d_out, int out_size){
    const float* emb = (const float*)d_in[0];
    const float* wq  = (const float*)d_in[1];
    const float* wk  = (const float*)d_in[2];
    const float* wv  = (const float*)d_in[3];
    const float* wo  = (const float*)d_in[4];
    const float* qnw = (const float*)d_in[5];
    const float* knw = (const float*)d_in[6];
    const float* ln1 = (const float*)d_in[7];
    const float* ln2 = (const float*)d_in[8];
    const float* wg  = (const float*)d_in[9];
    const float* wu  = (const float*)d_in[10];
    const float* wd  = (const float*)d_in[11];
    const float* nw  = (const float*)d_in[12];
    const int*   am  = (const int*)d_in[13];

    float *p_h, *p_qkv, *p_gu;
    __nv_bfloat16 *p_wt, *p_nbf, *p_cbf, *p_abf;
    cudaGetSymbolAddress((void**)&p_h,   g_h);
    cudaGetSymbolAddress((void**)&p_qkv, g_qkv);
    cudaGetSymbolAddress((void**)&p_gu,  g_gu);
    cudaGetSymbolAddress((void**)&p_wt,  g_wt);
    cudaGetSymbolAddress((void**)&p_nbf, g_nbf);
    cudaGetSymbolAddress((void**)&p_cbf, g_cbf);
    cudaGetSymbolAddress((void**)&p_abf, g_abf);

    cudaFuncSetAttribute(gemm_mma<0>, cudaFuncAttributeMaxDynamicSharedMemorySize, 65536);
    cudaFuncSetAttribute(gemm_mma<1>, cudaFuncAttributeMaxDynamicSharedMemorySize, 65536);
    cudaFuncSetAttribute(attn_k,      cudaFuncAttributeMaxDynamicSharedMemorySize, ATT_SMEM);

    cudaMemcpyAsync(p_h, emb, sizeof(float) * (size_t)NTOK * DD,
                    cudaMemcpyDeviceToDevice);

    dim3 tb(32, 8);
    for(int l = 0; l < LL; l++){
        __nv_bfloat16* wb = p_wt + (size_t)l * W2_LAYER;
        transpose_bf16<<<dim3(32, 32), tb>>>(wq + (size_t)l*1024*1024,
            wb + W2_QKV,                 wb + W2_QKV + 2097152,                 1024, 1024);
        transpose_bf16<<<dim3(16, 32), tb>>>(wk + (size_t)l*1024*512,
            wb + W2_QKV + 1048576,       wb + W2_QKV + 2097152 + 1048576,      1024, 512);
        transpose_bf16<<<dim3(16, 32), tb>>>(wv + (size_t)l*1024*512,
            wb + W2_QKV + 1572864,       wb + W2_QKV + 2097152 + 1572864,      1024, 512);
        transpose_bf16<<<dim3(32, 32), tb>>>(wo + (size_t)l*1024*1024,
            wb + W2_WO,                  wb + W2_WO + 1048576,                 1024, 1024);
        transpose_bf16<<<dim3(96, 32), tb>>>(wg + (size_t)l*1024*FFF,
            wb + W2_GU,                  wb + W2_GU + 6291456,                 1024, 3072);
        transpose_bf16<<<dim3(96, 32), tb>>>(wu + (size_t)l*1024*FFF,
            wb + W2_GU + 3145728,        wb + W2_GU + 6291456 + 3145728,       1024, 3072);
        transpose_bf16<<<dim3(32, 96), tb>>>(wd + (size_t)l*FFF*1024,
            wb + W2_DN,                  wb + W2_DN + 3145728,                 3072, 1024);
    }

    const size_t PL_D = (size_t)NTOK * DD;     // plane stride, width-1024 acts
    const size_t PL_F = (size_t)NTOK * FFF;    // plane stride, width-3072 acts

    for(int l = 0; l < LL; l++){
        __nv_bfloat16* wb = p_wt + (size_t)l * W2_LAYER;
        rmsnorm_k<1><<<NTOK, 256>>>(p_h, ln1 + (size_t)l * DD, nullptr,
                                    p_nbf, p_nbf + PL_D);
        gemm_mma<0><<<dim3(16, 32), 256, 65536>>>(p_nbf, PL_D, wb + W2_QKV,
                                                  p_qkv, 1024, QKVW);
        qknorm_rope_k<<<(NTOK * (HH + HKK)) / 4, 128>>>(qnw + (size_t)l * HDD,
                                                        knw + (size_t)l * HDD);
        attn_k<<<dim3(SS / 32, HH, Bb), 256, ATT_SMEM>>>(am,
                (l % 2 == 0) ? SS : WIN_, p_cbf, p_cbf + PL_D);
        gemm_mma<1><<<dim3(8, 32), 256, 65536>>>(p_cbf, PL_D, wb + W2_WO,
                                                 p_h, 1024, 1024);
        rmsnorm_k<1><<<NTOK, 256>>>(p_h, ln2 + (size_t)l * DD, nullptr,
                                    p_nbf, p_nbf + PL_D);
        gemm_mma<0><<<dim3(48, 32), 256, 65536>>>(p_nbf, PL_D, wb + W2_GU,
                                                  p_gu, 1024, GUW);
        silu_k<<<(int)(((size_t)NTOK * FFF / 4) / 256), 256>>>(p_abf, p_abf + PL_F);
        gemm_mma<1><<<dim3(8, 32), 256, 65536>>>(p_abf, PL_F, wb + W2_DN,
                                                 p_h, 3072, 1024);
    }
    rmsnorm_k<0><<<NTOK, 256>>>(p_h, nw, (float*)d_out, nullptr, nullptr);
}

// round 12
// speedup vs baseline: 3.7873x; 1.6091x over previous
#include <cuda_runtime.h>
#include <cuda_fp16.h>
#include <math.h>
#include <stdint.h>

#define Bb   4
#define SS   1024
#define DD   1024
#define HH   16
#define HKK  8
#define HDD  64
#define FFF  3072
#define LL   4
#define NTOK (Bb*SS)
#define WIN_ 12
#define QKVW 2048
#define GUW  6144

// ---------------- scratch (device globals; no allocations allowed) -----------
__device__ float g_h  [(size_t)NTOK*DD];
__device__ float g_qkv[(size_t)NTOK*QKVW];
__device__ float g_gu [(size_t)NTOK*GUW];
// fp16 activation planes
__device__ __half g_nh[(size_t)NTOK*DD];
__device__ __half g_ch[(size_t)NTOK*DD];
__device__ __half g_ah[(size_t)NTOK*FFF];

// fp16 weights transposed to [N][K]; per-layer element offsets:
#define W1_QKV   0
#define W1_WO    2097152
#define W1_GU    3145728
#define W1_DN    9437184
#define W1_LAYER 12582912
__device__ __half g_wt[(size_t)LL*W1_LAYER];

// ---------------- helpers -----------------------------------------------------
__device__ __forceinline__ uint32_t smem_u32(const void* p){
    uint32_t a;
    asm("{ .reg .u64 t; cvta.to.shared.u64 t, %1; cvt.u32.u64 %0, t; }" : "=r"(a) : "l"(p));
    return a;
}
__device__ __forceinline__ uint32_t packh(__half a, __half b){
    __half2 t(a, b);
    return *(uint32_t*)&t;
}
__device__ __forceinline__ uint2 pack4h(float4 v){
    return make_uint2(packh(__float2half_rn(v.x), __float2half_rn(v.y)),
                      packh(__float2half_rn(v.z), __float2half_rn(v.w)));
}

#define LDSM4(r, addr) \
    asm volatile("ldmatrix.sync.aligned.m8n8.x4.shared.b16 {%0,%1,%2,%3}, [%4];" \
        : "=r"((r)[0]), "=r"((r)[1]), "=r"((r)[2]), "=r"((r)[3]) : "r"(addr))

#define MMA16816(c, a, b0, b1) \
    asm volatile("mma.sync.aligned.m16n8k16.row.col.f32.f16.f16.f32 " \
        "{%0,%1,%2,%3}, {%4,%5,%6,%7}, {%8,%9}, {%0,%1,%2,%3};" \
        : "+f"((c)[0]), "+f"((c)[1]), "+f"((c)[2]), "+f"((c)[3]) \
        : "r"((a)[0]), "r"((a)[1]), "r"((a)[2]), "r"((a)[3]), "r"(b0), "r"(b1))

#define CPASYNC16(dst, src) \
    asm volatile("cp.async.cg.shared.global [%0], [%1], 16;" \
        :: "r"(dst), "l"((unsigned long long)__cvta_generic_to_global(src)))

// ============ GEMM: C[M,N] (+)= A[M,K] * Bt[N,K]^T, fp16 in / fp32 acc =======
// CTA tile 128x128, BK=32 per stage, 2 stages, 256 threads (8 warps = 4m x 2n).
// stage layout (fp16 elems, 8192/stage): A@0  B@4096.
// row = 32 elems (4 chunks of 16B); phys chunk = ch ^ ((row>>1)&3).
template<int ACC>
__global__ void __launch_bounds__(256, 2) gemm_mma(
        const __half* __restrict__ A, const __half* __restrict__ Bt,
        float* __restrict__ C, int K, int N){
    __shared__ __align__(16) __half smg[2*8192];
    const int tid = threadIdx.x, lane = tid & 31, wid = tid >> 5;
    const int wm = (wid >> 1) << 5, wn = (wid & 1) << 6;
    const int bm = blockIdx.y << 7, bn = blockIdx.x << 7;
    const uint32_t sb = smem_u32(smg);

    float c[2][8][4];
    #pragma unroll
    for(int i = 0; i < 2; i++)
        #pragma unroll
        for(int j = 0; j < 8; j++){
            c[i][j][0] = 0.f; c[i][j][1] = 0.f; c[i][j][2] = 0.f; c[i][j][3] = 0.f;
        }

    const int cid0 = tid << 1;
    auto prefetch = [&](int s, int kt){
        #pragma unroll
        for(int rg = 0; rg < 2; rg++){
            #pragma unroll
            for(int j = 0; j < 2; j++){
                int cid = cid0 | j;             // 0..511 per region
                int row = cid >> 2, ch = cid & 3;
                const __half* src = (rg ? Bt : A) +
                    (size_t)((rg ? bn : bm) + row) * K + kt * 32 + (ch << 3);
                uint32_t dst = sb + 2u * (uint32_t)(s * 8192 + rg * 4096 +
                               row * 32 + ((ch ^ ((row >> 1) & 3)) << 3));
                CPASYNC16(dst, src);
            }
        }
    };

    const int T = K >> 5;
    prefetch(0, 0);
    asm volatile("cp.async.commit_group;");

    for(int kt = 0; kt < T; kt++){
        const int s = kt & 1;
        if(kt + 1 < T){
            prefetch(s ^ 1, kt + 1);
            asm volatile("cp.async.commit_group;");
            asm volatile("cp.async.wait_group 1;");
        } else {
            asm volatile("cp.async.wait_group 0;");
        }
        __syncthreads();

        const uint32_t stg = sb + 2u * (uint32_t)(s * 8192);
        #pragma unroll
        for(int kk = 0; kk < 2; kk++){
            uint32_t a[2][4];
            #pragma unroll
            for(int mt = 0; mt < 2; mt++){
                int R = wm + mt * 16 + (lane & 15);
                int phys = (kk * 2 + (lane >> 4)) ^ ((R >> 1) & 3);
                LDSM4(a[mt], stg + 2u * (uint32_t)(R * 32 + (phys << 3)));
            }
            #pragma unroll
            for(int ng = 0; ng < 4; ng++){
                int R = wn + ng * 16 + (lane & 7) + ((lane >> 4) << 3);
                int phys = (kk * 2 + ((lane >> 3) & 1)) ^ ((R >> 1) & 3);
                uint32_t b[4];
                LDSM4(b, stg + 2u * (uint32_t)(4096 + R * 32 + (phys << 3)));
                #pragma unroll
                for(int mt = 0; mt < 2; mt++){
                    MMA16816(c[mt][2*ng],   a[mt], b[0], b[1]);
                    MMA16816(c[mt][2*ng+1], a[mt], b[2], b[3]);
                }
            }
        }
        __syncthreads();
    }

    // ---- epilogue ----
    #pragma unroll
    for(int mt = 0; mt < 2; mt++)
        #pragma unroll
        for(int nt = 0; nt < 8; nt++){
            int r  = bm + wm + mt * 16 + (lane >> 2);
            int cc = bn + wn + nt * 8 + ((lane & 3) << 1);
            float* p0 = C + (size_t)r * N + cc;
            float* p1 = C + (size_t)(r + 8) * N + cc;
            float2 v0 = make_float2(c[mt][nt][0], c[mt][nt][1]);
            float2 v1 = make_float2(c[mt][nt][2], c[mt][nt][3]);
            if(ACC){
                float2 o = *(const float2*)p0; v0.x += o.x; v0.y += o.y;
                o = *(const float2*)p1;        v1.x += o.x; v1.y += o.y;
            }
            *(float2*)p0 = v0;
            *(float2*)p1 = v1;
        }
}

// ---------------- transpose + fp16 convert: d[n][k] = fp16(src[k][n]) --------
__global__ void transpose_fp16(const float* __restrict__ src,
                               __half* __restrict__ dst, int K, int N){
    __shared__ float t[32][33];
    int k0 = blockIdx.y << 5, n0 = blockIdx.x << 5;
    int x = threadIdx.x, y = threadIdx.y;
    #pragma unroll
    for(int i = 0; i < 32; i += 8) t[y + i][x] = src[(size_t)(k0 + y + i) * N + n0 + x];
    __syncthreads();
    #pragma unroll
    for(int i = 0; i < 32; i += 8)
        dst[(size_t)(n0 + y + i) * K + k0 + x] = __float2half_rn(t[x][y + i]);
}

// ---------------- RMSNorm over rows of width DD ------------------------------
// HF=1: write fp16 plane; HF=0: write fp32
template<int HF>
__global__ void rmsnorm_k(const float* __restrict__ x, const float* __restrict__ w,
                          float* __restrict__ out, __half* __restrict__ oh){
    int row = blockIdx.x;
    const float4* xr = (const float4*)(x + (size_t)row * DD);
    float4 v = xr[threadIdx.x];
    float ss = v.x*v.x + v.y*v.y + v.z*v.z + v.w*v.w;
    __shared__ float red[8];
    #pragma unroll
    for(int o = 16; o; o >>= 1) ss += __shfl_xor_sync(~0u, ss, o);
    if((threadIdx.x & 31) == 0) red[threadIdx.x >> 5] = ss;
    __syncthreads();
    if(threadIdx.x < 8){
        float t = red[threadIdx.x];
        #pragma unroll
        for(int o = 4; o; o >>= 1) t += __shfl_xor_sync(0xff, t, o);
        if(threadIdx.x == 0) red[0] = rsqrtf(t / (float)DD + 1e-6f);
    }
    __syncthreads();
    float r = red[0];
    float4 wv = ((const float4*)w)[threadIdx.x];
    float4 o4 = make_float4(v.x*r*wv.x, v.y*r*wv.y, v.z*r*wv.z, v.w*r*wv.w);
    if(HF){
        *(uint2*)&oh[(size_t)row * DD + (threadIdx.x << 2)] = pack4h(o4);
    } else {
        ((float4*)(out + (size_t)row * DD))[threadIdx.x] = o4;
    }
}

// ---------------- fused per-head QK RMSNorm + RoPE (packed qkv) --------------
__global__ void qknorm_rope_k(const float* __restrict__ qw, const float* __restrict__ kw){
    int wid  = (blockIdx.x * blockDim.x + threadIdx.x) >> 5;
    int lane = threadIdx.x & 31;
    const int total = NTOK * (HH + HKK);
    if(wid >= total) return;
    int token = wid / (HH + HKK);
    int head  = wid % (HH + HKK);
    float* base; const float* wn;
    if(head < HH){ base = g_qkv + (size_t)token * QKVW + head * HDD; wn = qw; }
    else         { base = g_qkv + (size_t)token * QKVW + 1024 + (head - HH) * HDD; wn = kw; }
    int s = token & (SS - 1);
    float x0 = base[lane], x1 = base[lane + 32];
    float ss = x0*x0 + x1*x1;
    #pragma unroll
    for(int o = 16; o; o >>= 1) ss += __shfl_xor_sync(~0u, ss, o);
    float r = rsqrtf(ss / (float)HDD + 1e-6f);
    x0 = x0 * r * wn[lane];
    x1 = x1 * r * wn[lane + 32];
    float inv = expf(-(float)lane * 0.431734704963f);   // ln(1e6)/32
    float ang = (float)s * inv;
    float sn, cs; sincosf(ang, &sn, &cs);
    base[lane]      = x0 * cs - x1 * sn;
    base[lane + 32] = x1 * cs + x0 * sn;
}

// ---------------- attention: 32 queries/block, online softmax ----------------
__device__ __forceinline__ float warp_max(float v){
    #pragma unroll
    for(int o = 16; o; o >>= 1) v = fmaxf(v, __shfl_xor_sync(~0u, v, o));
    return v;
}
__device__ __forceinline__ float warp_sum(float v){
    #pragma unroll
    for(int o = 16; o; o >>= 1) v += __shfl_xor_sync(~0u, v, o);
    return v;
}

// dyn smem: Ks[64][65] Vs[64][65] qs[32][64] ps[32][64] msk[64]
#define ATT_SMEM ((4160*2 + 2048*2 + 64) * 4)
__global__ void __launch_bounds__(256) attn_k(const int* __restrict__ amask, int win,
        __half* __restrict__ ch){
    extern __shared__ float sm[];
    float (*Ks)[65] = (float(*)[65])sm;
    float (*Vs)[65] = (float(*)[65])(sm + 4160);
    float (*qs)[64] = (float(*)[64])(sm + 8320);
    float (*ps)[64] = (float(*)[64])(sm + 10368);
    int*   msk      = (int*)(sm + 12416);
    const int b = blockIdx.z, h = blockIdx.y;
    const int q0 = blockIdx.x << 5;
    const int kvh = h >> 1;
    const int tid = threadIdx.x, lane = tid & 31, w = tid >> 5;

    for(int e = tid; e < 32 * 64; e += 256){
        int r = e >> 6, d = e & 63;
        qs[r][d] = g_qkv[((size_t)(b * SS) + q0 + r) * QKVW + h * HDD + d];
    }
    const int qbase = q0 + 4 * w;
    float m[4], sum[4], c0[4], c1[4];
    #pragma unroll
    for(int i = 0; i < 4; i++){ m[i] = -1e30f; sum[i] = 0.f; c0[i] = 0.f; c1[i] = 0.f; }

    int kbeg = 0, kend = SS;
    if(win < SS){
        kbeg = max(0, q0 - win) & ~63;
        kend = min(SS, q0 + 31 + win + 1);
    }
    const bool full = (win >= SS);

    for(int kt = kbeg; kt < kend; kt += 64){
        for(int e = tid; e < 4096; e += 256){
            int r = e >> 6, d = e & 63;
            size_t gi = ((size_t)(b * SS) + kt + r) * QKVW + 1024 + kvh * HDD + d;
            Ks[r][d] = g_qkv[gi];
            Vs[r][d] = g_qkv[gi + 512];
        }
        if(tid < 64) msk[tid] = amask[b * SS + kt + tid];
        __syncthreads();

        float s[4][2];
        #pragma unroll
        for(int i = 0; i < 4; i++){ s[i][0] = 0.f; s[i][1] = 0.f; }
        #pragma unroll 8
        for(int d = 0; d < 64; d++){
            float ka = Ks[lane][d], kb = Ks[lane + 32][d];
            #pragma unroll
            for(int i = 0; i < 4; i++){
                float q = qs[4 * w + i][d];
                s[i][0] += q * ka;
                s[i][1] += q * kb;
            }
        }
        const float scale = 0.125f;
        const int j0 = kt + lane, j1 = j0 + 32;
        bool ok0 = msk[lane] > 0, ok1 = msk[lane + 32] > 0;
        #pragma unroll
        for(int i = 0; i < 4; i++){
            int qi = qbase + i;
            int d0 = abs(qi - j0), d1 = abs(qi - j1);
            float v0 = (ok0 && (full || d0 <= win)) ? s[i][0] * scale : -1e30f;
            float v1 = (ok1 && (full || d1 <= win)) ? s[i][1] * scale : -1e30f;
            float t = warp_max(fmaxf(v0, v1));
            float mn = fmaxf(m[i], t);
            float p0 = (v0 > -1e29f) ? expf(v0 - mn) : 0.f;
            float p1 = (v1 > -1e29f) ? expf(v1 - mn) : 0.f;
            float corr = expf(m[i] - mn);
            sum[i] = sum[i] * corr + warp_sum(p0 + p1);
            m[i] = mn;
            c0[i] *= corr; c1[i] *= corr;
            ps[4 * w + i][lane]      = p0;
            ps[4 * w + i][lane + 32] = p1;
        }
        __syncwarp();
        #pragma unroll 8
        for(int k = 0; k < 64; k++){
            float v0 = Vs[k][lane], v1 = Vs[k][lane + 32];
            #pragma unroll
            for(int i = 0; i < 4; i++){
                float p = ps[4 * w + i][k];
                c0[i] += p * v0;
                c1[i] += p * v1;
            }
        }
        __syncthreads();
    }

    #pragma unroll
    for(int i = 0; i < 4; i++){
        float r = (sum[i] > 0.f) ? 1.f / sum[i] : 0.f;
        size_t o = ((size_t)(b * SS) + qbase + i) * DD + h * HDD;
        ch[o + lane]      = __float2half_rn(c0[i] * r);
        ch[o + lane + 32] = __float2half_rn(c1[i] * r);
    }
}

// ---------------- SiLU(gate) * up -> fp16 plane ------------------------------
__global__ void silu_k(__half* __restrict__ oh){
    size_t i = (size_t)blockIdx.x * blockDim.x + threadIdx.x;   // float4 idx
    size_t row = i / (FFF/4);
    int    c   = (int)(i % (FFF/4));
    const float4* gp = (const float4*)(g_gu + row * GUW);
    float4 g = gp[c];
    float4 u = gp[c + FFF/4];
    g.x = g.x / (1.f + expf(-g.x)) * u.x;
    g.y = g.y / (1.f + expf(-g.y)) * u.y;
    g.z = g.z / (1.f + expf(-g.z)) * u.z;
    g.w = g.w / (1.f + expf(-g.w)) * u.w;
    *(uint2*)&oh[row * FFF + ((size_t)c << 2)] = pack4h(g);
}

// ---------------- driver -----------------------------------------------------
extern "C" void kernel_launch(void* const* d_in, const int* in_sizes, int n_in,
                              void* d_out, int out_size){
    const float* emb = (const float*)d_in[0];
    const float* wq  = (const float*)d_in[1];
    const float* wk  = (const float*)d_in[2];
    const float* wv  = (const float*)d_in[3];
    const float* wo  = (const float*)d_in[4];
    const float* qnw = (const float*)d_in[5];
    const float* knw = (const float*)d_in[6];
    const float* ln1 = (const float*)d_in[7];
    const float* ln2 = (const float*)d_in[8];
    const float* wg  = (const float*)d_in[9];
    const float* wu  = (const float*)d_in[10];
    const float* wd  = (const float*)d_in[11];
    const float* nw  = (const float*)d_in[12];
    const int*   am  = (const int*)d_in[13];

    float *p_h, *p_qkv, *p_gu;
    __half *p_wt, *p_nh, *p_ch, *p_ah;
    cudaGetSymbolAddress((void**)&p_h,   g_h);
    cudaGetSymbolAddress((void**)&p_qkv, g_qkv);
    cudaGetSymbolAddress((void**)&p_gu,  g_gu);
    cudaGetSymbolAddress((void**)&p_wt,  g_wt);
    cudaGetSymbolAddress((void**)&p_nh,  g_nh);
    cudaGetSymbolAddress((void**)&p_ch,  g_ch);
    cudaGetSymbolAddress((void**)&p_ah,  g_ah);

    cudaFuncSetAttribute(attn_k, cudaFuncAttributeMaxDynamicSharedMemorySize, ATT_SMEM);

    cudaMemcpyAsync(p_h, emb, sizeof(float) * (size_t)NTOK * DD,
                    cudaMemcpyDeviceToDevice);

    dim3 tb(32, 8);
    for(int l = 0; l < LL; l++){
        __half* wb = p_wt + (size_t)l * W1_LAYER;
        transpose_fp16<<<dim3(32, 32), tb>>>(wq + (size_t)l*1024*1024,
            wb + W1_QKV,             1024, 1024);
        transpose_fp16<<<dim3(16, 32), tb>>>(wk + (size_t)l*1024*512,
            wb + W1_QKV + 1048576,   1024, 512);
        transpose_fp16<<<dim3(16, 32), tb>>>(wv + (size_t)l*1024*512,
            wb + W1_QKV + 1572864,   1024, 512);
        transpose_fp16<<<dim3(32, 32), tb>>>(wo + (size_t)l*1024*1024,
            wb + W1_WO,              1024, 1024);
        transpose_fp16<<<dim3(96, 32), tb>>>(wg + (size_t)l*1024*FFF,
            wb + W1_GU,              1024, 3072);
        transpose_fp16<<<dim3(96, 32), tb>>>(wu + (size_t)l*1024*FFF,
            wb + W1_GU + 3145728,    1024, 3072);
        transpose_fp16<<<dim3(32, 96), tb>>>(wd + (size_t)l*FFF*1024,
            wb + W1_DN,              3072, 1024);
    }

    for(int l = 0; l < LL; l++){
        __half* wb = p_wt + (size_t)l * W1_LAYER;
        rmsnorm_k<1><<<NTOK, 256>>>(p_h, ln1 + (size_t)l * DD, nullptr, p_nh);
        gemm_mma<0><<<dim3(16, 32), 256>>>(p_nh, wb + W1_QKV, p_qkv, 1024, QKVW);
        qknorm_rope_k<<<(NTOK * (HH + HKK)) / 4, 128>>>(qnw + (size_t)l * HDD,
                                                        knw + (size_t)l * HDD);
        attn_k<<<dim3(SS / 32, HH, Bb), 256, ATT_SMEM>>>(am,
                (l % 2 == 0) ? SS : WIN_, p_ch);
        gemm_mma<1><<<dim3(8, 32), 256>>>(p_ch, wb + W1_WO, p_h, 1024, 1024);
        rmsnorm_k<1><<<NTOK, 256>>>(p_h, ln2 + (size_t)l * DD, nullptr, p_nh);
        gemm_mma<0><<<dim3(48, 32), 256>>>(p_nh, wb + W1_GU, p_gu, 1024, GUW);
        silu_k<<<(int)(((size_t)NTOK * FFF / 4) / 256), 256>>>(p_ah);
        gemm_mma<1><<<dim3(8, 32), 256>>>(p_ah, wb + W1_DN, p_h, 3072, 1024);
    }
    rmsnorm_k<0><<<NTOK, 256>>>(p_h, nw, (float*)d_out, nullptr);
}